// round 1
// baseline (speedup 1.0000x reference)
#include <cuda_runtime.h>
#include <cuda_bf16.h>
#include <cstdint>
#include <math.h>

#define DIMC 1024
#define NH   16
#define HD   64
#define NPOS 1024
#define BATCHN 16
#define KPROJ 512

// ---------------- scratch (device globals; allocation-free) ----------------
__device__ float g_q[BATCHN * DIMC * NPOS];            // (b, o, p) post elu+1
__device__ float g_k[BATCHN * DIMC * NPOS];            // (b, o, p) post elu+1
__device__ float g_km[BATCHN * DIMC];                  // mean over p of k
__device__ __nv_bfloat16 g_whi[2 * DIMC * KPROJ];
__device__ __nv_bfloat16 g_wlo[2 * DIMC * KPROJ];
__device__ float g_cos[(DIMC / 2) * NPOS];             // [j][p]
__device__ float g_sin[(DIMC / 2) * NPOS];
__device__ __nv_bfloat16 g_kvt_hi[BATCHN * NH * HD * HD];  // [b][h][e][d]
__device__ __nv_bfloat16 g_kvt_lo[BATCHN * NH * HD * HD];

// ---------------- helpers ----------------
__device__ __forceinline__ void mma16816(float c[4], const uint32_t a[4], const uint32_t b[2]) {
    asm volatile(
        "mma.sync.aligned.m16n8k16.row.col.f32.bf16.bf16.f32 "
        "{%0,%1,%2,%3}, {%4,%5,%6,%7}, {%8,%9}, {%0,%1,%2,%3};"
        : "+f"(c[0]), "+f"(c[1]), "+f"(c[2]), "+f"(c[3])
        : "r"(a[0]), "r"(a[1]), "r"(a[2]), "r"(a[3]), "r"(b[0]), "r"(b[1]));
}

__device__ __forceinline__ void split2(float v, __nv_bfloat16& hi, __nv_bfloat16& lo) {
    hi = __float2bfloat16(v);
    lo = __float2bfloat16(v - __bfloat162float(hi));
}

__device__ __forceinline__ uint32_t packbf(__nv_bfloat16 a, __nv_bfloat16 b) {
    return (uint32_t)__bfloat16_as_ushort(a) | ((uint32_t)__bfloat16_as_ushort(b) << 16);
}

__device__ __forceinline__ float elu1(float v) { return v > 0.f ? v + 1.f : expf(v); }

// ---------------- prep kernels ----------------
__global__ void prep_tables_kernel() {
    int idx = blockIdx.x * blockDim.x + threadIdx.x;   // over 512*1024
    if (idx >= (DIMC / 2) * NPOS) return;
    int j = idx >> 10, p = idx & (NPOS - 1);
    int jj = (j < 256) ? j : j - 256;
    float pos = (float)((j < 256) ? (p >> 5) : (p & 31));
    // theta = 10000^(-jj/256)
    float theta = expf(-(float)jj * (9.210340371976184f / 256.f));
    float ang = pos * theta;
    float s, c;
    sincosf(ang, &s, &c);
    g_cos[idx] = c;
    g_sin[idx] = s;
}

__global__ void prep_w_kernel(const float* __restrict__ qk_w) {
    int idx = blockIdx.x * blockDim.x + threadIdx.x;   // over 2048*512
    if (idx >= 2 * DIMC * KPROJ) return;
    __nv_bfloat16 hi, lo;
    split2(qk_w[idx], hi, lo);
    g_whi[idx] = hi;
    g_wlo[idx] = lo;
}

__global__ void prep_zero_kernel() {
    int idx = blockIdx.x * blockDim.x + threadIdx.x;
    if (idx < BATCHN * DIMC) g_km[idx] = 0.f;
}

// ---------------- projection GEMM: q/k = elu(W@x + b)+1, km via atomics ----------------
#define PA_STR 40
#define PB_STR 136

__global__ __launch_bounds__(256) void proj_kernel(const float* __restrict__ x,
                                                   const float* __restrict__ qk_b) {
    __shared__ __nv_bfloat16 sa[2][128 * PA_STR];   // W tile [o][c], hi/lo
    __shared__ __nv_bfloat16 sb[2][32 * PB_STR];    // X tile [c][p], hi/lo

    int tid = threadIdx.x;
    int lane = tid & 31, wid = tid >> 5;
    int wm = wid >> 2, wn = wid & 3;                // warps 2(m) x 4(n)
    int g4 = lane >> 2, tg = lane & 3;

    int pt = blockIdx.x, ot = blockIdx.y;
    int b = blockIdx.z >> 1, grp = blockIdx.z & 1;
    const __nv_bfloat16* Whi = g_whi + (size_t)grp * DIMC * KPROJ;
    const __nv_bfloat16* Wlo = g_wlo + (size_t)grp * DIMC * KPROJ;
    const float* X = x + ((size_t)b * DIMC + grp * KPROJ) * NPOS;
    int o0 = ot * 128, p0 = pt * 128;

    float c[4][4][4];
#pragma unroll
    for (int i = 0; i < 4; i++)
#pragma unroll
        for (int j = 0; j < 4; j++)
#pragma unroll
            for (int k = 0; k < 4; k++) c[i][j][k] = 0.f;

    for (int kt = 0; kt < 16; kt++) {
        int c0 = kt * 32;
        // stage A (W) tiles: 128x32 bf16, hi/lo
        for (int s = tid; s < 512; s += 256) {
            int o = s >> 2, cs = (s & 3) * 8;
            *(uint4*)&sa[0][o * PA_STR + cs] = *(const uint4*)&Whi[(size_t)(o0 + o) * KPROJ + c0 + cs];
            *(uint4*)&sa[1][o * PA_STR + cs] = *(const uint4*)&Wlo[(size_t)(o0 + o) * KPROJ + c0 + cs];
        }
        // stage B (X) tile: 32x128 fp32 -> bf16 hi/lo in [c][p]
        for (int s = tid; s < 1024; s += 256) {
            int cc = s >> 5, ps = (s & 31) * 4;
            float4 v = *(const float4*)&X[(size_t)(c0 + cc) * NPOS + p0 + ps];
            __nv_bfloat16 h0, l0, h1, l1, h2, l2, h3, l3;
            split2(v.x, h0, l0); split2(v.y, h1, l1); split2(v.z, h2, l2); split2(v.w, h3, l3);
            *(uint32_t*)&sb[0][cc * PB_STR + ps]     = packbf(h0, h1);
            *(uint32_t*)&sb[0][cc * PB_STR + ps + 2] = packbf(h2, h3);
            *(uint32_t*)&sb[1][cc * PB_STR + ps]     = packbf(l0, l1);
            *(uint32_t*)&sb[1][cc * PB_STR + ps + 2] = packbf(l2, l3);
        }
        __syncthreads();

#pragma unroll
        for (int ks = 0; ks < 2; ks++) {
            int kk = ks * 16;
            uint32_t ah[4][4], al[4][4];
#pragma unroll
            for (int mi = 0; mi < 4; mi++) {
                int r = wm * 64 + mi * 16 + g4;
                int col = kk + tg * 2;
                ah[mi][0] = *(uint32_t*)&sa[0][r * PA_STR + col];
                ah[mi][1] = *(uint32_t*)&sa[0][(r + 8) * PA_STR + col];
                ah[mi][2] = *(uint32_t*)&sa[0][r * PA_STR + col + 8];
                ah[mi][3] = *(uint32_t*)&sa[0][(r + 8) * PA_STR + col + 8];
                al[mi][0] = *(uint32_t*)&sa[1][r * PA_STR + col];
                al[mi][1] = *(uint32_t*)&sa[1][(r + 8) * PA_STR + col];
                al[mi][2] = *(uint32_t*)&sa[1][r * PA_STR + col + 8];
                al[mi][3] = *(uint32_t*)&sa[1][(r + 8) * PA_STR + col + 8];
            }
            uint32_t bh[4][2], bl[4][2];
            const unsigned short* SH = (const unsigned short*)sb[0];
            const unsigned short* SL = (const unsigned short*)sb[1];
#pragma unroll
            for (int ni = 0; ni < 4; ni++) {
                int p = wn * 32 + ni * 8 + g4;
                int k0 = kk + tg * 2;
                bh[ni][0] = (uint32_t)SH[k0 * PB_STR + p] | ((uint32_t)SH[(k0 + 1) * PB_STR + p] << 16);
                bh[ni][1] = (uint32_t)SH[(k0 + 8) * PB_STR + p] | ((uint32_t)SH[(k0 + 9) * PB_STR + p] << 16);
                bl[ni][0] = (uint32_t)SL[k0 * PB_STR + p] | ((uint32_t)SL[(k0 + 1) * PB_STR + p] << 16);
                bl[ni][1] = (uint32_t)SL[(k0 + 8) * PB_STR + p] | ((uint32_t)SL[(k0 + 9) * PB_STR + p] << 16);
            }
#pragma unroll
            for (int mi = 0; mi < 4; mi++)
#pragma unroll
                for (int ni = 0; ni < 4; ni++) {
                    mma16816(c[mi][ni], ah[mi], bh[ni]);
                    mma16816(c[mi][ni], ah[mi], bl[ni]);
                    mma16816(c[mi][ni], al[mi], bh[ni]);
                }
        }
        __syncthreads();
    }

    // epilogue: bias + elu + 1, store fp32, km atomics for k-group
    float* dst = (grp ? g_k : g_q) + (size_t)b * DIMC * NPOS;
#pragma unroll
    for (int mi = 0; mi < 4; mi++) {
        int r0 = o0 + wm * 64 + mi * 16 + g4;
        int r1 = r0 + 8;
        float bias0 = __ldg(&qk_b[grp * DIMC + r0]);
        float bias1 = __ldg(&qk_b[grp * DIMC + r1]);
        float rs0 = 0.f, rs1 = 0.f;
#pragma unroll
        for (int ni = 0; ni < 4; ni++) {
            int p = p0 + wn * 32 + ni * 8 + tg * 2;
            float v00 = elu1(c[mi][ni][0] + bias0);
            float v01 = elu1(c[mi][ni][1] + bias0);
            float v10 = elu1(c[mi][ni][2] + bias1);
            float v11 = elu1(c[mi][ni][3] + bias1);
            *(float2*)&dst[(size_t)r0 * NPOS + p] = make_float2(v00, v01);
            *(float2*)&dst[(size_t)r1 * NPOS + p] = make_float2(v10, v11);
            rs0 += v00 + v01;
            rs1 += v10 + v11;
        }
        if (grp) {
            rs0 += __shfl_xor_sync(0xffffffffu, rs0, 1);
            rs0 += __shfl_xor_sync(0xffffffffu, rs0, 2);
            rs1 += __shfl_xor_sync(0xffffffffu, rs1, 1);
            rs1 += __shfl_xor_sync(0xffffffffu, rs1, 2);
            if (tg == 0) {
                atomicAdd(&g_km[b * DIMC + r0], rs0 * (1.f / NPOS));
                atomicAdd(&g_km[b * DIMC + r1], rs1 * (1.f / NPOS));
            }
        }
    }
}

// ---------------- kv kernel: kv[d][e] = (1/n) sum_n rope(k)[d,n] * v[e,n] ----------------
#define KV_STR 66

__global__ __launch_bounds__(256) void kv_kernel(const float* __restrict__ x) {
    __shared__ __nv_bfloat16 sa[2][64 * KV_STR];   // k_rope [d][n] hi/lo
    __shared__ __nv_bfloat16 sb[2][64 * KV_STR];   // v      [e][n] hi/lo

    int tid = threadIdx.x;
    int lane = tid & 31, wid = tid >> 5;
    int wm = wid >> 2, wn = wid & 3;               // warps 2(d) x 4(e)
    int g4 = lane >> 2, tg = lane & 3;
    int bh = blockIdx.x;
    int b = bh >> 4, h = bh & 15;
    const float* Kp = g_k + ((size_t)b * DIMC + h * HD) * NPOS;
    const float* V  = x + ((size_t)b * DIMC + h * HD) * NPOS;

    float c[2][2][4];
#pragma unroll
    for (int i = 0; i < 2; i++)
#pragma unroll
        for (int j = 0; j < 2; j++)
#pragma unroll
            for (int k = 0; k < 4; k++) c[i][j][k] = 0.f;

    for (int ch = 0; ch < 16; ch++) {
        int n0 = ch * 64;
        // stage K with rope: pairs (2*d2, 2*d2+1)
        for (int i = tid; i < 32 * 64; i += 256) {
            int n = i & 63, d2 = i >> 6;
            float k0 = Kp[(size_t)(2 * d2) * NPOS + n0 + n];
            float k1 = Kp[(size_t)(2 * d2 + 1) * NPOS + n0 + n];
            int j = h * 32 + d2;
            float cs = g_cos[(size_t)j * NPOS + n0 + n];
            float sn = g_sin[(size_t)j * NPOS + n0 + n];
            float r0 = cs * k0 - sn * k1;
            float r1 = sn * k0 + cs * k1;
            __nv_bfloat16 h0, l0, h1, l1;
            split2(r0, h0, l0); split2(r1, h1, l1);
            sa[0][(2 * d2) * KV_STR + n] = h0;
            sa[0][(2 * d2 + 1) * KV_STR + n] = h1;
            sa[1][(2 * d2) * KV_STR + n] = l0;
            sa[1][(2 * d2 + 1) * KV_STR + n] = l1;
        }
        // stage V
        for (int i = tid; i < 64 * 64; i += 256) {
            int n = i & 63, e = i >> 6;
            float v = V[(size_t)e * NPOS + n0 + n];
            __nv_bfloat16 hv, lv;
            split2(v, hv, lv);
            sb[0][e * KV_STR + n] = hv;
            sb[1][e * KV_STR + n] = lv;
        }
        __syncthreads();

#pragma unroll
        for (int ks = 0; ks < 4; ks++) {
            int kk = ks * 16;
            uint32_t ah[2][4], al[2][4];
#pragma unroll
            for (int mi = 0; mi < 2; mi++) {
                int d = wm * 32 + mi * 16 + g4;
                int col = kk + tg * 2;
                ah[mi][0] = *(uint32_t*)&sa[0][d * KV_STR + col];
                ah[mi][1] = *(uint32_t*)&sa[0][(d + 8) * KV_STR + col];
                ah[mi][2] = *(uint32_t*)&sa[0][d * KV_STR + col + 8];
                ah[mi][3] = *(uint32_t*)&sa[0][(d + 8) * KV_STR + col + 8];
                al[mi][0] = *(uint32_t*)&sa[1][d * KV_STR + col];
                al[mi][1] = *(uint32_t*)&sa[1][(d + 8) * KV_STR + col];
                al[mi][2] = *(uint32_t*)&sa[1][d * KV_STR + col + 8];
                al[mi][3] = *(uint32_t*)&sa[1][(d + 8) * KV_STR + col + 8];
            }
            uint32_t bh2[2][2], bl2[2][2];
#pragma unroll
            for (int ni = 0; ni < 2; ni++) {
                int e = wn * 16 + ni * 8 + g4;
                int col = kk + tg * 2;
                bh2[ni][0] = *(uint32_t*)&sb[0][e * KV_STR + col];
                bh2[ni][1] = *(uint32_t*)&sb[0][e * KV_STR + col + 8];
                bl2[ni][0] = *(uint32_t*)&sb[1][e * KV_STR + col];
                bl2[ni][1] = *(uint32_t*)&sb[1][e * KV_STR + col + 8];
            }
#pragma unroll
            for (int mi = 0; mi < 2; mi++)
#pragma unroll
                for (int ni = 0; ni < 2; ni++) {
                    mma16816(c[mi][ni], ah[mi], bh2[ni]);
                    mma16816(c[mi][ni], ah[mi], bl2[ni]);
                    mma16816(c[mi][ni], al[mi], bh2[ni]);
                }
        }
        __syncthreads();
    }

    // epilogue: scale by 1/n, split, store transposed [e][d]
    __nv_bfloat16* KTh = g_kvt_hi + (size_t)bh * HD * HD;
    __nv_bfloat16* KTl = g_kvt_lo + (size_t)bh * HD * HD;
#pragma unroll
    for (int mi = 0; mi < 2; mi++) {
#pragma unroll
        for (int ni = 0; ni < 2; ni++) {
            int d0 = wm * 32 + mi * 16 + g4, d1 = d0 + 8;
            int e0 = wn * 16 + ni * 8 + tg * 2, e1 = e0 + 1;
            float vals[4] = {c[mi][ni][0], c[mi][ni][1], c[mi][ni][2], c[mi][ni][3]};
            int dd[4] = {d0, d0, d1, d1};
            int ee[4] = {e0, e1, e0, e1};
#pragma unroll
            for (int t = 0; t < 4; t++) {
                float v = vals[t] * (1.f / NPOS);
                __nv_bfloat16 hi, lo;
                split2(v, hi, lo);
                KTh[ee[t] * HD + dd[t]] = hi;
                KTl[ee[t] * HD + dd[t]] = lo;
            }
        }
    }
}

// ---------------- out kernel: out[n][e] = z[n] * sum_d rope(q)[d,n] kv[d][e] ----------------
#define OA_STR 66
#define OB_STR 72
#define OSMEM_BYTES (2 * 128 * OA_STR * 2 + 2 * 64 * OB_STR * 2 + 128 * 4)

__global__ __launch_bounds__(256) void out_kernel(float* __restrict__ out) {
    extern __shared__ __align__(16) char sm_raw[];
    __nv_bfloat16* sa_hi = (__nv_bfloat16*)sm_raw;            // [n][d] 128 x OA_STR
    __nv_bfloat16* sa_lo = sa_hi + 128 * OA_STR;
    __nv_bfloat16* skh = sa_lo + 128 * OA_STR;                // [e][d] 64 x OB_STR
    __nv_bfloat16* skl = skh + 64 * OB_STR;
    float* s_z = (float*)(skl + 64 * OB_STR);                 // [128]

    int tid = threadIdx.x;
    int lane = tid & 31, wid = tid >> 5;
    int wm = wid >> 1, wn = wid & 1;               // warps 4(n-rows) x 2(e)
    int g4 = lane >> 2, tg = lane & 3;

    int nt = blockIdx.x, bh = blockIdx.y;
    int b = bh >> 4, h = bh & 15;
    int n0 = nt * 128;
    const float* Q = g_q + ((size_t)b * DIMC + h * HD) * NPOS;
    const float* km = g_km + b * DIMC + h * HD;

    if (tid < 128) s_z[tid] = 0.f;
    // copy kv tiles (hi/lo) into padded smem
    {
        const uint4* KH = (const uint4*)(g_kvt_hi + (size_t)bh * HD * HD);
        const uint4* KL = (const uint4*)(g_kvt_lo + (size_t)bh * HD * HD);
        for (int i = tid; i < 512; i += 256) {
            int e = i >> 3, ds = (i & 7) * 8;
            *(uint4*)&skh[e * OB_STR + ds] = KH[i];
            *(uint4*)&skl[e * OB_STR + ds] = KL[i];
        }
    }
    __syncthreads();

    // stage q: rope + split + z partials
#pragma unroll 4
    for (int pass = 0; pass < 16; pass++) {
        int d2 = (tid >> 7) + pass * 2;
        int n = tid & 127;
        float q0 = Q[(size_t)(2 * d2) * NPOS + n0 + n];
        float q1 = Q[(size_t)(2 * d2 + 1) * NPOS + n0 + n];
        float km0 = __ldg(&km[2 * d2]);
        float km1 = __ldg(&km[2 * d2 + 1]);
        atomicAdd(&s_z[n], q0 * km0 + q1 * km1);
        int j = h * 32 + d2;
        float cs = g_cos[(size_t)j * NPOS + n0 + n];
        float sn = g_sin[(size_t)j * NPOS + n0 + n];
        float r0 = cs * q0 - sn * q1;
        float r1 = sn * q0 + cs * q1;
        __nv_bfloat16 h0, l0, h1, l1;
        split2(r0, h0, l0); split2(r1, h1, l1);
        *(uint32_t*)&sa_hi[n * OA_STR + 2 * d2] = packbf(h0, h1);
        *(uint32_t*)&sa_lo[n * OA_STR + 2 * d2] = packbf(l0, l1);
    }
    __syncthreads();

    float c[2][4][4];
#pragma unroll
    for (int i = 0; i < 2; i++)
#pragma unroll
        for (int j = 0; j < 4; j++)
#pragma unroll
            for (int k = 0; k < 4; k++) c[i][j][k] = 0.f;

#pragma unroll
    for (int ks = 0; ks < 4; ks++) {
        int kk = ks * 16;
        uint32_t ah[2][4], al[2][4];
#pragma unroll
        for (int mi = 0; mi < 2; mi++) {
            int n = wm * 32 + mi * 16 + g4;
            int col = kk + tg * 2;
            ah[mi][0] = *(uint32_t*)&sa_hi[n * OA_STR + col];
            ah[mi][1] = *(uint32_t*)&sa_hi[(n + 8) * OA_STR + col];
            ah[mi][2] = *(uint32_t*)&sa_hi[n * OA_STR + col + 8];
            ah[mi][3] = *(uint32_t*)&sa_hi[(n + 8) * OA_STR + col + 8];
            al[mi][0] = *(uint32_t*)&sa_lo[n * OA_STR + col];
            al[mi][1] = *(uint32_t*)&sa_lo[(n + 8) * OA_STR + col];
            al[mi][2] = *(uint32_t*)&sa_lo[n * OA_STR + col + 8];
            al[mi][3] = *(uint32_t*)&sa_lo[(n + 8) * OA_STR + col + 8];
        }
        uint32_t bh2[4][2], bl2[4][2];
#pragma unroll
        for (int ni = 0; ni < 4; ni++) {
            int e = wn * 32 + ni * 8 + g4;
            int col = kk + tg * 2;
            bh2[ni][0] = *(uint32_t*)&skh[e * OB_STR + col];
            bh2[ni][1] = *(uint32_t*)&skh[e * OB_STR + col + 8];
            bl2[ni][0] = *(uint32_t*)&skl[e * OB_STR + col];
            bl2[ni][1] = *(uint32_t*)&skl[e * OB_STR + col + 8];
        }
#pragma unroll
        for (int mi = 0; mi < 2; mi++)
#pragma unroll
            for (int ni = 0; ni < 4; ni++) {
                mma16816(c[mi][ni], ah[mi], bh2[ni]);
                mma16816(c[mi][ni], ah[mi], bl2[ni]);
                mma16816(c[mi][ni], al[mi], bh2[ni]);
            }
    }

    // epilogue: z scaling, direct coalesced-sector STG
    float* O = out + ((size_t)b * DIMC + h * HD) * NPOS;
#pragma unroll
    for (int mi = 0; mi < 2; mi++) {
        int nr0 = wm * 32 + mi * 16 + g4;
        int nr1 = nr0 + 8;
        float z0 = 1.f / (s_z[nr0] + 1e-6f);
        float z1 = 1.f / (s_z[nr1] + 1e-6f);
#pragma unroll
        for (int ni = 0; ni < 4; ni++) {
            int e = wn * 32 + ni * 8 + tg * 2;
            O[(size_t)e * NPOS + n0 + nr0]       = c[mi][ni][0] * z0;
            O[(size_t)(e + 1) * NPOS + n0 + nr0] = c[mi][ni][1] * z0;
            O[(size_t)e * NPOS + n0 + nr1]       = c[mi][ni][2] * z1;
            O[(size_t)(e + 1) * NPOS + n0 + nr1] = c[mi][ni][3] * z1;
        }
    }
}

// ---------------- lepe: depthwise 3x3 SAME + bias, accumulate into out ----------------
__global__ __launch_bounds__(256) void lepe_kernel(const float* __restrict__ x,
                                                   const float* __restrict__ w,
                                                   const float* __restrict__ bias,
                                                   float* __restrict__ out) {
    __shared__ float sp[1024];
    int pc = blockIdx.x;                 // b*DIMC + c plane index
    int cch = pc & (DIMC - 1);
    const float* xp = x + (size_t)pc * 1024;
    int tid = threadIdx.x;
    for (int i = tid; i < 1024; i += 256) sp[i] = xp[i];
    __syncthreads();
    float wv[9];
#pragma unroll
    for (int k = 0; k < 9; k++) wv[k] = __ldg(&w[cch * 9 + k]);
    float bs = __ldg(&bias[cch]);
    for (int i = tid; i < 1024; i += 256) {
        int y = i >> 5, xx = i & 31;
        float acc = bs;
#pragma unroll
        for (int dy = -1; dy <= 1; dy++) {
            int yy = y + dy;
            if (yy < 0 || yy > 31) continue;
#pragma unroll
            for (int dx = -1; dx <= 1; dx++) {
                int x2 = xx + dx;
                if (x2 < 0 || x2 > 31) continue;
                acc += wv[(dy + 1) * 3 + (dx + 1)] * sp[yy * 32 + x2];
            }
        }
        out[(size_t)pc * 1024 + i] += acc;
    }
}

// ---------------- launch ----------------
extern "C" void kernel_launch(void* const* d_in, const int* in_sizes, int n_in,
                              void* d_out, int out_size) {
    const float* x      = (const float*)d_in[0];
    const float* qk_w   = (const float*)d_in[1];
    const float* qk_b   = (const float*)d_in[2];
    const float* lepe_w = (const float*)d_in[3];
    const float* lepe_b = (const float*)d_in[4];
    float* out = (float*)d_out;

    cudaFuncSetAttribute(out_kernel, cudaFuncAttributeMaxDynamicSharedMemorySize, OSMEM_BYTES);

    prep_tables_kernel<<<(DIMC / 2) * NPOS / 256, 256>>>();
    prep_w_kernel<<<2 * DIMC * KPROJ / 256, 256>>>(qk_w);
    prep_zero_kernel<<<BATCHN * DIMC / 256, 256>>>();

    proj_kernel<<<dim3(8, 8, 2 * BATCHN), 256>>>(x, qk_b);
    kv_kernel<<<BATCHN * NH, 256>>>(x);
    out_kernel<<<dim3(8, BATCHN * NH), 256, OSMEM_BYTES>>>(out);
    lepe_kernel<<<BATCHN * DIMC, 256>>>(x, lepe_w, lepe_b, out);
}